// round 15
// baseline (speedup 1.0000x reference)
#include <cuda_runtime.h>
#include <cuda_bf16.h>
#include <math_constants.h>

#define DIM 1024
#define NHEADS 16
#define HDIM 64
#define B 2
#define S 2048
#define M_TOT (B * S)            // 4096
#define EPS 1e-6f

// ---------------- scratch (static device globals; no allocation) ----------------
__device__ float g_qkv[(size_t)M_TOT * 3 * DIM];           // [4096, 3072]
__device__ float g_q[(size_t)B * NHEADS * S * HDIM];       // [B,H,S,D] (tf32-rounded)
__device__ float g_k[(size_t)B * NHEADS * S * HDIM];
__device__ float g_v[(size_t)B * NHEADS * S * HDIM];
__device__ float g_o[(size_t)M_TOT * DIM];                 // attn out (tf32-rounded)
__device__ float g_xr[(size_t)M_TOT * DIM];                // x, tf32-rounded
__device__ float g_wqkvr[(size_t)3 * DIM * DIM];           // w_qkv, tf32-rounded
__device__ float g_wprojr[(size_t)DIM * DIM];              // w_proj, tf32-rounded

// ---- helpers --------------------------------------------------------------------
__device__ __forceinline__ unsigned f2tf32(float x) {
    unsigned u;
    asm("cvt.rna.tf32.f32 %0, %1;" : "=r"(u) : "f"(x));
    return u;
}
__device__ __forceinline__ float f2tf32f(float x) { return __uint_as_float(f2tf32(x)); }
__device__ __forceinline__ void mma_tf32(float c[4],
                                         unsigned a0, unsigned a1, unsigned a2, unsigned a3,
                                         unsigned b0, unsigned b1) {
    asm volatile(
        "mma.sync.aligned.m16n8k8.row.col.f32.tf32.tf32.f32 "
        "{%0,%1,%2,%3}, {%4,%5,%6,%7}, {%8,%9}, {%0,%1,%2,%3};"
        : "+f"(c[0]), "+f"(c[1]), "+f"(c[2]), "+f"(c[3])
        : "r"(a0), "r"(a1), "r"(a2), "r"(a3), "r"(b0), "r"(b1));
}
__device__ __forceinline__ void cp16(void* sdst, const void* gsrc) {
    unsigned sa = (unsigned)__cvta_generic_to_shared(sdst);
    asm volatile("cp.async.cg.shared.global [%0], [%1], 16;\n" :: "r"(sa), "l"(gsrc));
}
#define CP_COMMIT() asm volatile("cp.async.commit_group;\n" ::: "memory")
#define CP_WAIT0()  asm volatile("cp.async.wait_group 0;\n" ::: "memory")

// ---------------- Kernel 0: elementwise tf32 pre-round ---------------------------
__global__ void __launch_bounds__(256) round_tf32_kernel(const float4* __restrict__ in,
                                                         float4* __restrict__ out, int n4) {
    int i = blockIdx.x * blockDim.x + threadIdx.x;
    if (i < n4) {
        float4 v = in[i];
        v.x = f2tf32f(v.x); v.y = f2tf32f(v.y);
        v.z = f2tf32f(v.z); v.w = f2tf32f(v.w);
        out[i] = v;
    }
}

// ---------------- Kernel 1/4: tf32 GEMM NT, 256x128 tile, cp.async DB ------------
// Inputs pre-rounded to tf32: fragment loads are plain LDS, zero cvts in loop.
#define GSTR 36
#define GABUF (256 * GSTR)
#define GBBUF (128 * GSTR)
__global__ void __launch_bounds__(256) gemm_tf32(const float* __restrict__ A,
                                                 const float* __restrict__ Bm,
                                                 const float* __restrict__ bias,
                                                 float* __restrict__ C,
                                                 int M, int N, int K) {
    extern __shared__ float gsm[];
    float* As = gsm;                  // [2][256][GSTR]
    float* Bs = gsm + 2 * GABUF;      // [2][128][GSTR]

    const int bn = blockIdx.x * 128;
    const int bm = blockIdx.y * 256;
    const int tid = threadIdx.x;
    const int warp = tid >> 5;
    const int lane = tid & 31;
    const int wm = (warp >> 1) * 64;   // 0,64,128,192
    const int wn = (warp & 1) * 64;    // 0,64
    const int qr = lane >> 2;
    const int ql = lane & 3;

    float acc[4][8][4];
#pragma unroll
    for (int mt = 0; mt < 4; mt++)
#pragma unroll
        for (int nt = 0; nt < 8; nt++)
#pragma unroll
            for (int e = 0; e < 4; e++) acc[mt][nt][e] = 0.f;

    auto issue_tile = [&](int k0, int buf) {
        float* Ad = As + buf * GABUF;
        float* Bd = Bs + buf * GBBUF;
#pragma unroll
        for (int i = 0; i < 8; i++) {
            int c = tid + i * 256;
            int row = c >> 3, ch = (c & 7) * 4;
            cp16(&Ad[row * GSTR + ch], A + (size_t)(bm + row) * K + k0 + ch);
        }
#pragma unroll
        for (int i = 0; i < 4; i++) {
            int c = tid + i * 256;
            int row = c >> 3, ch = (c & 7) * 4;
            cp16(&Bd[row * GSTR + ch], Bm + (size_t)(bn + row) * K + k0 + ch);
        }
        CP_COMMIT();
    };

    issue_tile(0, 0);
    const int nit = K >> 5;
    for (int it = 0; it < nit; it++) {
        CP_WAIT0();
        __syncthreads();
        if (it + 1 < nit) issue_tile((it + 1) << 5, (it + 1) & 1);

        const float* Ac = As + (it & 1) * GABUF;
        const float* Bc = Bs + (it & 1) * GBBUF;
#pragma unroll
        for (int kc = 0; kc < 4; kc++) {
            const int ko = kc * 8;
            unsigned af[4][4];
#pragma unroll
            for (int mt = 0; mt < 4; mt++) {
                int r = wm + mt * 16 + qr;
                af[mt][0] = __float_as_uint(Ac[r * GSTR + ko + ql]);
                af[mt][1] = __float_as_uint(Ac[(r + 8) * GSTR + ko + ql]);
                af[mt][2] = __float_as_uint(Ac[r * GSTR + ko + ql + 4]);
                af[mt][3] = __float_as_uint(Ac[(r + 8) * GSTR + ko + ql + 4]);
            }
#pragma unroll
            for (int nt = 0; nt < 8; nt++) {
                int cb = wn + nt * 8 + qr;
                unsigned b0 = __float_as_uint(Bc[cb * GSTR + ko + ql]);
                unsigned b1 = __float_as_uint(Bc[cb * GSTR + ko + ql + 4]);
#pragma unroll
                for (int mt = 0; mt < 4; mt++)
                    mma_tf32(acc[mt][nt], af[mt][0], af[mt][1], af[mt][2], af[mt][3], b0, b1);
            }
        }
        __syncthreads();
    }

    // epilogue
#pragma unroll
    for (int mt = 0; mt < 4; mt++) {
        int r0 = bm + wm + mt * 16 + qr;
#pragma unroll
        for (int nt = 0; nt < 8; nt++) {
            int c0 = bn + wn + nt * 8 + ql * 2;
            float bz0 = bias ? bias[c0] : 0.f;
            float bz1 = bias ? bias[c0 + 1] : 0.f;
            float2 o0 = {acc[mt][nt][0] + bz0, acc[mt][nt][1] + bz1};
            float2 o1 = {acc[mt][nt][2] + bz0, acc[mt][nt][3] + bz1};
            *(float2*)(C + (size_t)r0 * N + c0) = o0;
            *(float2*)(C + (size_t)(r0 + 8) * N + c0) = o1;
        }
    }
}

// ---------------- Kernel 2/4: LN + RoPE, warp-per-head; outputs tf32-rounded -----
__global__ void __launch_bounds__(512) ln_rope_kernel(const float* __restrict__ qkv,
                                                      const float* __restrict__ qg,
                                                      const float* __restrict__ qb,
                                                      const float* __restrict__ kg,
                                                      const float* __restrict__ kb) {
    const int m = blockIdx.x;              // b*S + s
    const int h = threadIdx.x >> 5;
    const int lane = threadIdx.x & 31;
    const int b = m / S;
    const int s = m % S;

    const float* row = qkv + (size_t)m * (3 * DIM) + h * HDIM;
    float q0 = row[lane],           q1 = row[lane + 32];
    float k0 = row[DIM + lane],     k1 = row[DIM + lane + 32];
    float v0 = row[2 * DIM + lane], v1 = row[2 * DIM + lane + 32];

    float sq = q0 + q1, sq2 = q0 * q0 + q1 * q1;
    float sk = k0 + k1, sk2 = k0 * k0 + k1 * k1;
#pragma unroll
    for (int o = 16; o; o >>= 1) {
        sq  += __shfl_xor_sync(0xffffffffu, sq, o);
        sq2 += __shfl_xor_sync(0xffffffffu, sq2, o);
        sk  += __shfl_xor_sync(0xffffffffu, sk, o);
        sk2 += __shfl_xor_sync(0xffffffffu, sk2, o);
    }
    float muq = sq * (1.f / HDIM);
    float rq = rsqrtf(sq2 * (1.f / HDIM) - muq * muq + EPS);
    float muk = sk * (1.f / HDIM);
    float rk = rsqrtf(sk2 * (1.f / HDIM) - muk * muk + EPS);

    float qn0 = (q0 - muq) * rq * qg[lane] + qb[lane];
    float qn1 = (q1 - muq) * rq * qg[lane + 32] + qb[lane + 32];
    float kn0 = (k0 - muk) * rk * kg[lane] + kb[lane];
    float kn1 = (k1 - muk) * rk * kg[lane + 32] + kb[lane + 32];

    float inv = powf(10000.f, -(float)lane * (1.f / 32.f));
    float c, sn;
    sincosf((float)s * inv, &sn, &c);
    float qo0 = (qn0 * c - qn1 * sn) * 0.125f;
    float qo1 = (qn1 * c + qn0 * sn) * 0.125f;
    float ko0 = kn0 * c - kn1 * sn;
    float ko1 = kn1 * c + kn0 * sn;

    const size_t idx = (((size_t)(b * NHEADS + h)) * S + s) * HDIM;
    g_q[idx + lane] = f2tf32f(qo0);  g_q[idx + lane + 32] = f2tf32f(qo1);
    g_k[idx + lane] = f2tf32f(ko0);  g_k[idx + lane + 32] = f2tf32f(ko1);
    g_v[idx + lane] = f2tf32f(v0);   g_v[idx + lane + 32] = f2tf32f(v1);
}

// ---------------- Kernel 3/4: flash attention, tf32, Q-frags in registers --------
// Q/K/V pre-rounded by ln_rope: staging is plain copies, zero cvts except P.
#define AQ 128
#define AKT 64
#define ASTR 68
#define KVBUF (AKT * ASTR)
__global__ void __launch_bounds__(256) attn_tc(const float* __restrict__ Q,
                                               const float* __restrict__ K,
                                               const float* __restrict__ V,
                                               float* __restrict__ O) {
    extern __shared__ float sm[];
    float* Qs = sm;                       // [128][68] (reused as Ps after Q-frag hoist)
    float* Ks = Qs + AQ * ASTR;           // [2][64][68]  (key, dim)
    float* Vs = Ks + 2 * KVBUF;           // [2][64][68]  (dim, key) transposed
    float* Ps = Qs;                       // alias: Qs dead after fragment hoist

    const int bh = blockIdx.y;
    const int qt = blockIdx.x;
    const int b = bh / NHEADS;
    const int h = bh % NHEADS;

    const float* Qg = Q + ((size_t)bh * S + qt * AQ) * HDIM;
    const float* Kg = K + (size_t)bh * S * HDIM;
    const float* Vg = V + (size_t)bh * S * HDIM;

    const int tid = threadIdx.x;
    const int warp = tid >> 5;
    const int lane = tid & 31;
    const int wq = warp * 16;
    const int qr = lane >> 2;       // 0..7
    const int ql = lane & 3;        // 0..3
    const int lr = tid >> 4;        // 0..15 row group for loads
    const int lc4 = (tid & 15) * 4; // col*4 for loads

    // load Q tile (128x64), already tf32-rounded
#pragma unroll
    for (int i = 0; i < 8; i++) {
        int r = lr + i * 16;
        *(float4*)(&Qs[r * ASTR + lc4]) = *(const float4*)(Qg + r * HDIM + lc4);
    }

    float ofrag[8][4];
#pragma unroll
    for (int dt = 0; dt < 8; dt++)
#pragma unroll
        for (int e = 0; e < 4; e++) ofrag[dt][e] = 0.f;
    float mrow0 = -CUDART_INF_F, mrow1 = -CUDART_INF_F;
    float lrow0 = 0.f, lrow1 = 0.f;

    float4 kr[4], vr[4];
#pragma unroll
    for (int i = 0; i < 4; i++) {
        int r = lr + i * 16;
        kr[i] = *(const float4*)(Kg + r * HDIM + lc4);
        vr[i] = *(const float4*)(Vg + r * HDIM + lc4);
    }
#pragma unroll
    for (int i = 0; i < 4; i++) {
        int r = lr + i * 16;
        *(float4*)(&Ks[r * ASTR + lc4]) = kr[i];
        Vs[(lc4 + 0) * ASTR + r] = vr[i].x;
        Vs[(lc4 + 1) * ASTR + r] = vr[i].y;
        Vs[(lc4 + 2) * ASTR + r] = vr[i].z;
        Vs[(lc4 + 3) * ASTR + r] = vr[i].w;
    }
    __syncthreads();

    // hoist Q fragments into registers (Qs smem becomes Ps after this)
    unsigned qfrag[8][4];
    {
        const int r = wq + qr;
#pragma unroll
        for (int kc = 0; kc < 8; kc++) {
            const int ko = kc * 8;
            qfrag[kc][0] = __float_as_uint(Qs[r * ASTR + ko + ql]);
            qfrag[kc][1] = __float_as_uint(Qs[(r + 8) * ASTR + ko + ql]);
            qfrag[kc][2] = __float_as_uint(Qs[r * ASTR + ko + ql + 4]);
            qfrag[kc][3] = __float_as_uint(Qs[(r + 8) * ASTR + ko + ql + 4]);
        }
    }
    // no sync needed: each warp's Qs reads and Ps writes cover the same 16-row band

    const int nkt = S / AKT;
    for (int kt = 0; kt < nkt; kt++) {
        const int cur = kt & 1;
        if (kt + 1 < nkt) {
            const float* Kt = Kg + (size_t)(kt + 1) * AKT * HDIM;
            const float* Vt = Vg + (size_t)(kt + 1) * AKT * HDIM;
#pragma unroll
            for (int i = 0; i < 4; i++) {
                int r = lr + i * 16;
                kr[i] = *(const float4*)(Kt + r * HDIM + lc4);
                vr[i] = *(const float4*)(Vt + r * HDIM + lc4);
            }
        }
        const float* Kc = Ks + cur * KVBUF;
        const float* Vc = Vs + cur * KVBUF;

        // ---- scores: 16 x 64 per warp ----
        float sf[8][4];
#pragma unroll
        for (int nt = 0; nt < 8; nt++)
#pragma unroll
            for (int e = 0; e < 4; e++) sf[nt][e] = 0.f;

#pragma unroll
        for (int kc = 0; kc < 8; kc++) {
            const int ko = kc * 8;
#pragma unroll
            for (int nt = 0; nt < 8; nt++) {
                int cb = nt * 8 + qr;
                unsigned b0 = __float_as_uint(Kc[cb * ASTR + ko + ql]);
                unsigned b1 = __float_as_uint(Kc[cb * ASTR + ko + ql + 4]);
                mma_tf32(sf[nt], qfrag[kc][0], qfrag[kc][1], qfrag[kc][2], qfrag[kc][3], b0, b1);
            }
        }

        // ---- online softmax ----
        float mx0 = -CUDART_INF_F, mx1 = -CUDART_INF_F;
#pragma unroll
        for (int nt = 0; nt < 8; nt++) {
            mx0 = fmaxf(mx0, fmaxf(sf[nt][0], sf[nt][1]));
            mx1 = fmaxf(mx1, fmaxf(sf[nt][2], sf[nt][3]));
        }
        mx0 = fmaxf(mx0, __shfl_xor_sync(0xffffffffu, mx0, 1));
        mx0 = fmaxf(mx0, __shfl_xor_sync(0xffffffffu, mx0, 2));
        mx1 = fmaxf(mx1, __shfl_xor_sync(0xffffffffu, mx1, 1));
        mx1 = fmaxf(mx1, __shfl_xor_sync(0xffffffffu, mx1, 2));
        float nm0 = fmaxf(mrow0, mx0);
        float nm1 = fmaxf(mrow1, mx1);
        float corr0 = __expf(mrow0 - nm0);
        float corr1 = __expf(mrow1 - nm1);

        float sum0 = 0.f, sum1 = 0.f;
        const int r1 = wq + qr, r2 = r1 + 8;
#pragma unroll
        for (int nt = 0; nt < 8; nt++) {
            float p0 = __expf(sf[nt][0] - nm0);
            float p1 = __expf(sf[nt][1] - nm0);
            float p2 = __expf(sf[nt][2] - nm1);
            float p3 = __expf(sf[nt][3] - nm1);
            sum0 += p0 + p1;
            sum1 += p2 + p3;
            int c = nt * 8 + ql * 2;
            float2 s01 = {f2tf32f(p0), f2tf32f(p1)};
            float2 s23 = {f2tf32f(p2), f2tf32f(p3)};
            *(float2*)(&Ps[r1 * ASTR + c]) = s01;
            *(float2*)(&Ps[r2 * ASTR + c]) = s23;
        }
        sum0 += __shfl_xor_sync(0xffffffffu, sum0, 1);
        sum0 += __shfl_xor_sync(0xffffffffu, sum0, 2);
        sum1 += __shfl_xor_sync(0xffffffffu, sum1, 1);
        sum1 += __shfl_xor_sync(0xffffffffu, sum1, 2);
        lrow0 = lrow0 * corr0 + sum0;
        lrow1 = lrow1 * corr1 + sum1;
        mrow0 = nm0; mrow1 = nm1;
#pragma unroll
        for (int dt = 0; dt < 8; dt++) {
            ofrag[dt][0] *= corr0; ofrag[dt][1] *= corr0;
            ofrag[dt][2] *= corr1; ofrag[dt][3] *= corr1;
        }
        __syncwarp();

        // ---- PV: O[16 x 64] += P[16 x 64] @ V[64 x 64] ----
#pragma unroll
        for (int kc = 0; kc < 8; kc++) {
            const int ko = kc * 8;
            unsigned a0 = __float_as_uint(Ps[r1 * ASTR + ko + ql]);
            unsigned a1 = __float_as_uint(Ps[r2 * ASTR + ko + ql]);
            unsigned a2 = __float_as_uint(Ps[r1 * ASTR + ko + ql + 4]);
            unsigned a3 = __float_as_uint(Ps[r2 * ASTR + ko + ql + 4]);
#pragma unroll
            for (int dt = 0; dt < 8; dt++) {
                int db = dt * 8 + qr;
                unsigned b0 = __float_as_uint(Vc[db * ASTR + ko + ql]);
                unsigned b1 = __float_as_uint(Vc[db * ASTR + ko + ql + 4]);
                mma_tf32(ofrag[dt], a0, a1, a2, a3, b0, b1);
            }
        }

        // store prefetched tile into the other buffer
        if (kt + 1 < nkt) {
            const int nxt = (kt + 1) & 1;
            float* Kn = Ks + nxt * KVBUF;
            float* Vn = Vs + nxt * KVBUF;
#pragma unroll
            for (int i = 0; i < 4; i++) {
                int r = lr + i * 16;
                *(float4*)(&Kn[r * ASTR + lc4]) = kr[i];
                Vn[(lc4 + 0) * ASTR + r] = vr[i].x;
                Vn[(lc4 + 1) * ASTR + r] = vr[i].y;
                Vn[(lc4 + 2) * ASTR + r] = vr[i].z;
                Vn[(lc4 + 3) * ASTR + r] = vr[i].w;
            }
        }
        __syncthreads();
    }

    // epilogue: write to [B,S,C] at column h*64, tf32-rounded for the proj GEMM
    const float inv0 = 1.f / lrow0;
    const float inv1 = 1.f / lrow1;
    const int r1g = qt * AQ + wq + qr;
#pragma unroll
    for (int dt = 0; dt < 8; dt++) {
        int c = dt * 8 + ql * 2;
        size_t o1 = ((size_t)b * S + r1g) * DIM + h * HDIM + c;
        size_t o2 = ((size_t)b * S + r1g + 8) * DIM + h * HDIM + c;
        float2 w1 = {f2tf32f(ofrag[dt][0] * inv0), f2tf32f(ofrag[dt][1] * inv0)};
        float2 w2 = {f2tf32f(ofrag[dt][2] * inv1), f2tf32f(ofrag[dt][3] * inv1)};
        *(float2*)(O + o1) = w1;
        *(float2*)(O + o2) = w2;
    }
}

// ---------------- launch ---------------------------------------------------------
extern "C" void kernel_launch(void* const* d_in, const int* in_sizes, int n_in,
                              void* d_out, int out_size) {
    const float* x      = (const float*)d_in[0];
    const float* w_qkv  = (const float*)d_in[1];
    const float* w_proj = (const float*)d_in[2];
    const float* b_proj = (const float*)d_in[3];
    const float* q_g    = (const float*)d_in[4];
    const float* q_b    = (const float*)d_in[5];
    const float* k_g    = (const float*)d_in[6];
    const float* k_b    = (const float*)d_in[7];
    float* out = (float*)d_out;

    float *p_qkv, *p_q, *p_k, *p_v, *p_o, *p_xr, *p_wq, *p_wp;
    cudaGetSymbolAddress((void**)&p_qkv, g_qkv);
    cudaGetSymbolAddress((void**)&p_q, g_q);
    cudaGetSymbolAddress((void**)&p_k, g_k);
    cudaGetSymbolAddress((void**)&p_v, g_v);
    cudaGetSymbolAddress((void**)&p_o, g_o);
    cudaGetSymbolAddress((void**)&p_xr, g_xr);
    cudaGetSymbolAddress((void**)&p_wq, g_wqkvr);
    cudaGetSymbolAddress((void**)&p_wp, g_wprojr);

    // 0) pre-round x / w_qkv / w_proj to tf32 (bit-identical to in-loop rounding)
    round_tf32_kernel<<<(M_TOT * DIM / 4 + 255) / 256, 256>>>(
        (const float4*)x, (float4*)p_xr, M_TOT * DIM / 4);
    round_tf32_kernel<<<(3 * DIM * DIM / 4 + 255) / 256, 256>>>(
        (const float4*)w_qkv, (float4*)p_wq, 3 * DIM * DIM / 4);
    round_tf32_kernel<<<(DIM * DIM / 4 + 255) / 256, 256>>>(
        (const float4*)w_proj, (float4*)p_wp, DIM * DIM / 4);

    const int gemm_smem = (2 * GABUF + 2 * GBBUF) * sizeof(float);  // ~110 KB
    cudaFuncSetAttribute(gemm_tf32, cudaFuncAttributeMaxDynamicSharedMemorySize, gemm_smem);

    // 1) QKV projection: [4096,3072] = x @ w_qkv^T
    gemm_tf32<<<dim3(3 * DIM / 128, M_TOT / 256), 256, gemm_smem>>>(
        p_xr, p_wq, nullptr, p_qkv, M_TOT, 3 * DIM, DIM);

    // 2) LN + RoPE + scale + transpose to [B,H,S,D] (tf32-rounded outputs)
    ln_rope_kernel<<<M_TOT, 512>>>(p_qkv, q_g, q_b, k_g, k_b);

    // 3) flash attention (tensor core, Q frags in regs, double-buffered K/V)
    const int attn_smem = (AQ * ASTR + 4 * KVBUF) * sizeof(float);  // ~104 KB
    cudaFuncSetAttribute(attn_tc, cudaFuncAttributeMaxDynamicSharedMemorySize, attn_smem);
    attn_tc<<<dim3(S / AQ, B * NHEADS), 256, attn_smem>>>(p_q, p_k, p_v, p_o);

    // 4) output projection: out = O @ w_proj^T + b_proj
    gemm_tf32<<<dim3(DIM / 128, M_TOT / 256), 256, gemm_smem>>>(
        p_o, p_wp, b_proj, out, M_TOT, DIM, DIM);
}

// round 17
// speedup vs baseline: 1.0458x; 1.0458x over previous
#include <cuda_runtime.h>
#include <cuda_bf16.h>
#include <math_constants.h>

#define DIM 1024
#define NHEADS 16
#define HDIM 64
#define B 2
#define S 2048
#define M_TOT (B * S)            // 4096
#define EPS 1e-6f

// ---------------- scratch (static device globals; no allocation) ----------------
__device__ float g_qkv[(size_t)M_TOT * 3 * DIM];           // [4096, 3072]
__device__ float g_q[(size_t)B * NHEADS * S * HDIM];       // [B,H,S,D] (tf32-rounded)
__device__ float g_k[(size_t)B * NHEADS * S * HDIM];
__device__ float g_v[(size_t)B * NHEADS * S * HDIM];
__device__ float g_o[(size_t)M_TOT * DIM];                 // attn out (tf32-rounded)
__device__ float g_xr[(size_t)M_TOT * DIM];                // x, tf32-rounded
__device__ float g_wqkvr[(size_t)3 * DIM * DIM];           // w_qkv, tf32-rounded
__device__ float g_wprojr[(size_t)DIM * DIM];              // w_proj, tf32-rounded

// ---- helpers --------------------------------------------------------------------
__device__ __forceinline__ unsigned f2tf32(float x) {
    unsigned u;
    asm("cvt.rna.tf32.f32 %0, %1;" : "=r"(u) : "f"(x));
    return u;
}
__device__ __forceinline__ float f2tf32f(float x) { return __uint_as_float(f2tf32(x)); }
__device__ __forceinline__ void mma_tf32(float c[4],
                                         unsigned a0, unsigned a1, unsigned a2, unsigned a3,
                                         unsigned b0, unsigned b1) {
    asm volatile(
        "mma.sync.aligned.m16n8k8.row.col.f32.tf32.tf32.f32 "
        "{%0,%1,%2,%3}, {%4,%5,%6,%7}, {%8,%9}, {%0,%1,%2,%3};"
        : "+f"(c[0]), "+f"(c[1]), "+f"(c[2]), "+f"(c[3])
        : "r"(a0), "r"(a1), "r"(a2), "r"(a3), "r"(b0), "r"(b1));
}
// ldmatrix x4: four 8x8 b16 tiles == four 8x4 tf32 tiles; lane l of tile t gets
// tf32 element [l/4][l%4] — exactly the m16n8k8 tf32 fragment layout.
__device__ __forceinline__ void ldsm4(unsigned r[4], unsigned a) {
    asm volatile("ldmatrix.sync.aligned.m8n8.x4.shared.b16 {%0,%1,%2,%3}, [%4];"
                 : "=r"(r[0]), "=r"(r[1]), "=r"(r[2]), "=r"(r[3]) : "r"(a));
}
__device__ __forceinline__ void cp16(void* sdst, const void* gsrc) {
    unsigned sa = (unsigned)__cvta_generic_to_shared(sdst);
    asm volatile("cp.async.cg.shared.global [%0], [%1], 16;\n" :: "r"(sa), "l"(gsrc));
}
#define CP_COMMIT() asm volatile("cp.async.commit_group;\n" ::: "memory")
#define CP_WAIT0()  asm volatile("cp.async.wait_group 0;\n" ::: "memory")

// ---------------- Kernel 0: elementwise tf32 pre-round ---------------------------
__global__ void __launch_bounds__(256) round_tf32_kernel(const float4* __restrict__ in,
                                                         float4* __restrict__ out, int n4) {
    int i = blockIdx.x * blockDim.x + threadIdx.x;
    if (i < n4) {
        float4 v = in[i];
        v.x = f2tf32f(v.x); v.y = f2tf32f(v.y);
        v.z = f2tf32f(v.z); v.w = f2tf32f(v.w);
        out[i] = v;
    }
}

// ---------------- Kernel 1/4: tf32 GEMM NT, 256x128 tile, cp.async + ldmatrix ----
#define GSTR 36
#define GABUF (256 * GSTR)
#define GBBUF (128 * GSTR)
__global__ void __launch_bounds__(256) gemm_tf32(const float* __restrict__ A,
                                                 const float* __restrict__ Bm,
                                                 const float* __restrict__ bias,
                                                 float* __restrict__ C,
                                                 int M, int N, int K) {
    extern __shared__ float gsm[];
    float* As = gsm;                  // [2][256][GSTR]
    float* Bs = gsm + 2 * GABUF;      // [2][128][GSTR]

    const int bn = blockIdx.x * 128;
    const int bm = blockIdx.y * 256;
    const int tid = threadIdx.x;
    const int warp = tid >> 5;
    const int lane = tid & 31;
    const int wm = (warp >> 1) * 64;   // 0,64,128,192
    const int wn = (warp & 1) * 64;    // 0,64
    const int qr = lane >> 2;
    const int ql = lane & 3;
    const int g  = lane >> 3;          // ldmatrix tile index 0..3
    const int i8 = lane & 7;           // row within tile

    float acc[4][8][4];
#pragma unroll
    for (int mt = 0; mt < 4; mt++)
#pragma unroll
        for (int nt = 0; nt < 8; nt++)
#pragma unroll
            for (int e = 0; e < 4; e++) acc[mt][nt][e] = 0.f;

    // ldmatrix per-lane byte offsets (within one buffer)
    int aoff[4], boff[4];
#pragma unroll
    for (int mt = 0; mt < 4; mt++)      // A tiles: {r0-7,k0-3},{r8-15,k0-3},{r0-7,k4-7},{r8-15,k4-7}
        aoff[mt] = ((wm + mt * 16 + i8 + (g & 1) * 8) * GSTR + (g >> 1) * 4) * 4;
#pragma unroll
    for (int p = 0; p < 4; p++)         // B pair tiles: {n0-7,k0-3},{n0-7,k4-7},{n8-15,k0-3},{n8-15,k4-7}
        boff[p] = ((wn + p * 16 + i8 + (g >> 1) * 8) * GSTR + (g & 1) * 4) * 4;
    const unsigned sAs = (unsigned)__cvta_generic_to_shared(As);
    const unsigned sBs = (unsigned)__cvta_generic_to_shared(Bs);

    auto issue_tile = [&](int k0, int buf) {
        float* Ad = As + buf * GABUF;
        float* Bd = Bs + buf * GBBUF;
#pragma unroll
        for (int i = 0; i < 8; i++) {
            int c = tid + i * 256;
            int row = c >> 3, ch = (c & 7) * 4;
            cp16(&Ad[row * GSTR + ch], A + (size_t)(bm + row) * K + k0 + ch);
        }
#pragma unroll
        for (int i = 0; i < 4; i++) {
            int c = tid + i * 256;
            int row = c >> 3, ch = (c & 7) * 4;
            cp16(&Bd[row * GSTR + ch], Bm + (size_t)(bn + row) * K + k0 + ch);
        }
        CP_COMMIT();
    };

    issue_tile(0, 0);
    const int nit = K >> 5;
    for (int it = 0; it < nit; it++) {
        CP_WAIT0();
        __syncthreads();
        if (it + 1 < nit) issue_tile((it + 1) << 5, (it + 1) & 1);

        const unsigned AcS = sAs + (it & 1) * (GABUF * 4);
        const unsigned BcS = sBs + (it & 1) * (GBBUF * 4);
#pragma unroll
        for (int kc = 0; kc < 4; kc++) {
            const int kb = kc * 32;      // 8 floats = 32 bytes
            unsigned af[4][4], bf[4][4];
#pragma unroll
            for (int mt = 0; mt < 4; mt++) ldsm4(af[mt], AcS + aoff[mt] + kb);
#pragma unroll
            for (int p = 0; p < 4; p++)  ldsm4(bf[p], BcS + boff[p] + kb);
#pragma unroll
            for (int p = 0; p < 4; p++) {
#pragma unroll
                for (int mt = 0; mt < 4; mt++)
                    mma_tf32(acc[mt][2 * p], af[mt][0], af[mt][1], af[mt][2], af[mt][3],
                             bf[p][0], bf[p][1]);
#pragma unroll
                for (int mt = 0; mt < 4; mt++)
                    mma_tf32(acc[mt][2 * p + 1], af[mt][0], af[mt][1], af[mt][2], af[mt][3],
                             bf[p][2], bf[p][3]);
            }
        }
        __syncthreads();
    }

    // epilogue
#pragma unroll
    for (int mt = 0; mt < 4; mt++) {
        int r0 = bm + wm + mt * 16 + qr;
#pragma unroll
        for (int nt = 0; nt < 8; nt++) {
            int c0 = bn + wn + nt * 8 + ql * 2;
            float bz0 = bias ? bias[c0] : 0.f;
            float bz1 = bias ? bias[c0 + 1] : 0.f;
            float2 o0 = {acc[mt][nt][0] + bz0, acc[mt][nt][1] + bz1};
            float2 o1 = {acc[mt][nt][2] + bz0, acc[mt][nt][3] + bz1};
            *(float2*)(C + (size_t)r0 * N + c0) = o0;
            *(float2*)(C + (size_t)(r0 + 8) * N + c0) = o1;
        }
    }
}

// ---------------- Kernel 2/4: LN + RoPE, warp-per-head; outputs tf32-rounded -----
__global__ void __launch_bounds__(512) ln_rope_kernel(const float* __restrict__ qkv,
                                                      const float* __restrict__ qg,
                                                      const float* __restrict__ qb,
                                                      const float* __restrict__ kg,
                                                      const float* __restrict__ kb) {
    const int m = blockIdx.x;              // b*S + s
    const int h = threadIdx.x >> 5;
    const int lane = threadIdx.x & 31;
    const int b = m / S;
    const int s = m % S;

    const float* row = qkv + (size_t)m * (3 * DIM) + h * HDIM;
    float q0 = row[lane],           q1 = row[lane + 32];
    float k0 = row[DIM + lane],     k1 = row[DIM + lane + 32];
    float v0 = row[2 * DIM + lane], v1 = row[2 * DIM + lane + 32];

    float sq = q0 + q1, sq2 = q0 * q0 + q1 * q1;
    float sk = k0 + k1, sk2 = k0 * k0 + k1 * k1;
#pragma unroll
    for (int o = 16; o; o >>= 1) {
        sq  += __shfl_xor_sync(0xffffffffu, sq, o);
        sq2 += __shfl_xor_sync(0xffffffffu, sq2, o);
        sk  += __shfl_xor_sync(0xffffffffu, sk, o);
        sk2 += __shfl_xor_sync(0xffffffffu, sk2, o);
    }
    float muq = sq * (1.f / HDIM);
    float rq = rsqrtf(sq2 * (1.f / HDIM) - muq * muq + EPS);
    float muk = sk * (1.f / HDIM);
    float rk = rsqrtf(sk2 * (1.f / HDIM) - muk * muk + EPS);

    float qn0 = (q0 - muq) * rq * qg[lane] + qb[lane];
    float qn1 = (q1 - muq) * rq * qg[lane + 32] + qb[lane + 32];
    float kn0 = (k0 - muk) * rk * kg[lane] + kb[lane];
    float kn1 = (k1 - muk) * rk * kg[lane + 32] + kb[lane + 32];

    float inv = powf(10000.f, -(float)lane * (1.f / 32.f));
    float c, sn;
    sincosf((float)s * inv, &sn, &c);
    float qo0 = (qn0 * c - qn1 * sn) * 0.125f;
    float qo1 = (qn1 * c + qn0 * sn) * 0.125f;
    float ko0 = kn0 * c - kn1 * sn;
    float ko1 = kn1 * c + kn0 * sn;

    const size_t idx = (((size_t)(b * NHEADS + h)) * S + s) * HDIM;
    g_q[idx + lane] = f2tf32f(qo0);  g_q[idx + lane + 32] = f2tf32f(qo1);
    g_k[idx + lane] = f2tf32f(ko0);  g_k[idx + lane + 32] = f2tf32f(ko1);
    g_v[idx + lane] = f2tf32f(v0);   g_v[idx + lane + 32] = f2tf32f(v1);
}

// ---------------- Kernel 3/4: flash attention, tf32 + ldmatrix -------------------
#define AQ 128
#define AKT 64
#define ASTR 68
#define KVBUF (AKT * ASTR)
__global__ void __launch_bounds__(256) attn_tc(const float* __restrict__ Q,
                                               const float* __restrict__ K,
                                               const float* __restrict__ V,
                                               float* __restrict__ O) {
    extern __shared__ float sm[];
    float* Qs = sm;                       // [128][68] (reused as Ps after Q-frag hoist)
    float* Ks = Qs + AQ * ASTR;           // [2][64][68]  (key, dim)
    float* Vs = Ks + 2 * KVBUF;           // [2][64][68]  (dim, key) transposed
    float* Ps = Qs;                       // alias: Qs dead after fragment hoist

    const int bh = blockIdx.y;
    const int qt = blockIdx.x;
    const int b = bh / NHEADS;
    const int h = bh % NHEADS;

    const float* Qg = Q + ((size_t)bh * S + qt * AQ) * HDIM;
    const float* Kg = K + (size_t)bh * S * HDIM;
    const float* Vg = V + (size_t)bh * S * HDIM;

    const int tid = threadIdx.x;
    const int warp = tid >> 5;
    const int lane = tid & 31;
    const int wq = warp * 16;
    const int qr = lane >> 2;       // 0..7
    const int ql = lane & 3;        // 0..3
    const int g  = lane >> 3;
    const int i8 = lane & 7;
    const int lr = tid >> 4;        // 0..15 row group for loads
    const int lc4 = (tid & 15) * 4; // col*4 for loads

    // ldmatrix per-lane byte offsets
    const int offA = ((wq + i8 + (g & 1) * 8) * ASTR + (g >> 1) * 4) * 4;  // 16x8 A tile at row wq
    int offP[4];                                                            // B pair tiles (rows p*16..)
#pragma unroll
    for (int p = 0; p < 4; p++)
        offP[p] = ((p * 16 + i8 + (g >> 1) * 8) * ASTR + (g & 1) * 4) * 4;
    const unsigned sQsS = (unsigned)__cvta_generic_to_shared(Qs);
    const unsigned sKsS = (unsigned)__cvta_generic_to_shared(Ks);
    const unsigned sVsS = (unsigned)__cvta_generic_to_shared(Vs);

    // load Q tile (128x64), already tf32-rounded
#pragma unroll
    for (int i = 0; i < 8; i++) {
        int r = lr + i * 16;
        *(float4*)(&Qs[r * ASTR + lc4]) = *(const float4*)(Qg + r * HDIM + lc4);
    }

    float ofrag[8][4];
#pragma unroll
    for (int dt = 0; dt < 8; dt++)
#pragma unroll
        for (int e = 0; e < 4; e++) ofrag[dt][e] = 0.f;
    float mrow0 = -CUDART_INF_F, mrow1 = -CUDART_INF_F;
    float lrow0 = 0.f, lrow1 = 0.f;

    float4 kr[4], vr[4];
#pragma unroll
    for (int i = 0; i < 4; i++) {
        int r = lr + i * 16;
        kr[i] = *(const float4*)(Kg + r * HDIM + lc4);
        vr[i] = *(const float4*)(Vg + r * HDIM + lc4);
    }
#pragma unroll
    for (int i = 0; i < 4; i++) {
        int r = lr + i * 16;
        *(float4*)(&Ks[r * ASTR + lc4]) = kr[i];
        Vs[(lc4 + 0) * ASTR + r] = vr[i].x;
        Vs[(lc4 + 1) * ASTR + r] = vr[i].y;
        Vs[(lc4 + 2) * ASTR + r] = vr[i].z;
        Vs[(lc4 + 3) * ASTR + r] = vr[i].w;
    }
    __syncthreads();

    // hoist Q fragments into registers via ldmatrix (Qs smem becomes Ps after this)
    unsigned qfrag[8][4];
#pragma unroll
    for (int kc = 0; kc < 8; kc++) ldsm4(qfrag[kc], sQsS + offA + kc * 32);
    // no sync needed: each warp's Qs reads and Ps writes cover the same 16-row band

    const int nkt = S / AKT;
    for (int kt = 0; kt < nkt; kt++) {
        const int cur = kt & 1;
        if (kt + 1 < nkt) {
            const float* Kt = Kg + (size_t)(kt + 1) * AKT * HDIM;
            const float* Vt = Vg + (size_t)(kt + 1) * AKT * HDIM;
#pragma unroll
            for (int i = 0; i < 4; i++) {
                int r = lr + i * 16;
                kr[i] = *(const float4*)(Kt + r * HDIM + lc4);
                vr[i] = *(const float4*)(Vt + r * HDIM + lc4);
            }
        }
        const unsigned KcS = sKsS + cur * (KVBUF * 4);
        const unsigned VcS = sVsS + cur * (KVBUF * 4);

        // ---- scores: 16 x 64 per warp ----
        float sf[8][4];
#pragma unroll
        for (int nt = 0; nt < 8; nt++)
#pragma unroll
            for (int e = 0; e < 4; e++) sf[nt][e] = 0.f;

#pragma unroll
        for (int kc = 0; kc < 8; kc++) {
            const int kb = kc * 32;
#pragma unroll
            for (int p = 0; p < 4; p++) {
                unsigned bf[4];
                ldsm4(bf, KcS + offP[p] + kb);
                mma_tf32(sf[2 * p], qfrag[kc][0], qfrag[kc][1], qfrag[kc][2], qfrag[kc][3],
                         bf[0], bf[1]);
                mma_tf32(sf[2 * p + 1], qfrag[kc][0], qfrag[kc][1], qfrag[kc][2], qfrag[kc][3],
                         bf[2], bf[3]);
            }
        }

        // ---- online softmax ----
        float mx0 = -CUDART_INF_F, mx1 = -CUDART_INF_F;
#pragma unroll
        for (int nt = 0; nt < 8; nt++) {
            mx0 = fmaxf(mx0, fmaxf(sf[nt][0], sf[nt][1]));
            mx1 = fmaxf(mx1, fmaxf(sf[nt][2], sf[nt][3]));
        }
        mx0 = fmaxf(mx0, __shfl_xor_sync(0xffffffffu, mx0, 1));
        mx0 = fmaxf(mx0, __shfl_xor_sync(0xffffffffu, mx0, 2));
        mx1 = fmaxf(mx1, __shfl_xor_sync(0xffffffffu, mx1, 1));
        mx1 = fmaxf(mx1, __shfl_xor_sync(0xffffffffu, mx1, 2));
        float nm0 = fmaxf(mrow0, mx0);
        float nm1 = fmaxf(mrow1, mx1);
        float corr0 = __expf(mrow0 - nm0);
        float corr1 = __expf(mrow1 - nm1);

        float sum0 = 0.f, sum1 = 0.f;
        const int r1 = wq + qr, r2 = r1 + 8;
#pragma unroll
        for (int nt = 0; nt < 8; nt++) {
            float p0 = __expf(sf[nt][0] - nm0);
            float p1 = __expf(sf[nt][1] - nm0);
            float p2 = __expf(sf[nt][2] - nm1);
            float p3 = __expf(sf[nt][3] - nm1);
            sum0 += p0 + p1;
            sum1 += p2 + p3;
            int c = nt * 8 + ql * 2;
            float2 s01 = {f2tf32f(p0), f2tf32f(p1)};
            float2 s23 = {f2tf32f(p2), f2tf32f(p3)};
            *(float2*)(&Ps[r1 * ASTR + c]) = s01;
            *(float2*)(&Ps[r2 * ASTR + c]) = s23;
        }
        sum0 += __shfl_xor_sync(0xffffffffu, sum0, 1);
        sum0 += __shfl_xor_sync(0xffffffffu, sum0, 2);
        sum1 += __shfl_xor_sync(0xffffffffu, sum1, 1);
        sum1 += __shfl_xor_sync(0xffffffffu, sum1, 2);
        lrow0 = lrow0 * corr0 + sum0;
        lrow1 = lrow1 * corr1 + sum1;
        mrow0 = nm0; mrow1 = nm1;
#pragma unroll
        for (int dt = 0; dt < 8; dt++) {
            ofrag[dt][0] *= corr0; ofrag[dt][1] *= corr0;
            ofrag[dt][2] *= corr1; ofrag[dt][3] *= corr1;
        }
        __syncwarp();

        // ---- PV: O[16 x 64] += P[16 x 64] @ V[64 x 64] ----
#pragma unroll
        for (int kc = 0; kc < 8; kc++) {
            const int kb = kc * 32;
            unsigned pa[4];
            ldsm4(pa, sQsS + offA + kb);       // Ps aliases Qs
#pragma unroll
            for (int p = 0; p < 4; p++) {
                unsigned vf[4];
                ldsm4(vf, VcS + offP[p] + kb);
                mma_tf32(ofrag[2 * p], pa[0], pa[1], pa[2], pa[3], vf[0], vf[1]);
                mma_tf32(ofrag[2 * p + 1], pa[0], pa[1], pa[2], pa[3], vf[2], vf[3]);
            }
        }

        // store prefetched tile into the other buffer
        if (kt + 1 < nkt) {
            const int nxt = (kt + 1) & 1;
            float* Kn = Ks + nxt * KVBUF;
            float* Vn = Vs + nxt * KVBUF;
#pragma unroll
            for (int i = 0; i < 4; i++) {
                int r = lr + i * 16;
                *(float4*)(&Kn[r * ASTR + lc4]) = kr[i];
                Vn[(lc4 + 0) * ASTR + r] = vr[i].x;
                Vn[(lc4 + 1) * ASTR + r] = vr[i].y;
                Vn[(lc4 + 2) * ASTR + r] = vr[i].z;
                Vn[(lc4 + 3) * ASTR + r] = vr[i].w;
            }
        }
        __syncthreads();
    }

    // epilogue: write to [B,S,C] at column h*64, tf32-rounded for the proj GEMM
    const float inv0 = 1.f / lrow0;
    const float inv1 = 1.f / lrow1;
    const int r1g = qt * AQ + wq + qr;
#pragma unroll
    for (int dt = 0; dt < 8; dt++) {
        int c = dt * 8 + ql * 2;
        size_t o1 = ((size_t)b * S + r1g) * DIM + h * HDIM + c;
        size_t o2 = ((size_t)b * S + r1g + 8) * DIM + h * HDIM + c;
        float2 w1 = {f2tf32f(ofrag[dt][0] * inv0), f2tf32f(ofrag[dt][1] * inv0)};
        float2 w2 = {f2tf32f(ofrag[dt][2] * inv1), f2tf32f(ofrag[dt][3] * inv1)};
        *(float2*)(O + o1) = w1;
        *(float2*)(O + o2) = w2;
    }
}

// ---------------- launch ---------------------------------------------------------
extern "C" void kernel_launch(void* const* d_in, const int* in_sizes, int n_in,
                              void* d_out, int out_size) {
    const float* x      = (const float*)d_in[0];
    const float* w_qkv  = (const float*)d_in[1];
    const float* w_proj = (const float*)d_in[2];
    const float* b_proj = (const float*)d_in[3];
    const float* q_g    = (const float*)d_in[4];
    const float* q_b    = (const float*)d_in[5];
    const float* k_g    = (const float*)d_in[6];
    const float* k_b    = (const float*)d_in[7];
    float* out = (float*)d_out;

    float *p_qkv, *p_q, *p_k, *p_v, *p_o, *p_xr, *p_wq, *p_wp;
    cudaGetSymbolAddress((void**)&p_qkv, g_qkv);
    cudaGetSymbolAddress((void**)&p_q, g_q);
    cudaGetSymbolAddress((void**)&p_k, g_k);
    cudaGetSymbolAddress((void**)&p_v, g_v);
    cudaGetSymbolAddress((void**)&p_o, g_o);
    cudaGetSymbolAddress((void**)&p_xr, g_xr);
    cudaGetSymbolAddress((void**)&p_wq, g_wqkvr);
    cudaGetSymbolAddress((void**)&p_wp, g_wprojr);

    // 0) pre-round x / w_qkv / w_proj to tf32 (bit-identical to in-loop rounding)
    round_tf32_kernel<<<(M_TOT * DIM / 4 + 255) / 256, 256>>>(
        (const float4*)x, (float4*)p_xr, M_TOT * DIM / 4);
    round_tf32_kernel<<<(3 * DIM * DIM / 4 + 255) / 256, 256>>>(
        (const float4*)w_qkv, (float4*)p_wq, 3 * DIM * DIM / 4);
    round_tf32_kernel<<<(DIM * DIM / 4 + 255) / 256, 256>>>(
        (const float4*)w_proj, (float4*)p_wp, DIM * DIM / 4);

    const int gemm_smem = (2 * GABUF + 2 * GBBUF) * sizeof(float);  // ~110 KB
    cudaFuncSetAttribute(gemm_tf32, cudaFuncAttributeMaxDynamicSharedMemorySize, gemm_smem);

    // 1) QKV projection: [4096,3072] = x @ w_qkv^T
    gemm_tf32<<<dim3(3 * DIM / 128, M_TOT / 256), 256, gemm_smem>>>(
        p_xr, p_wq, nullptr, p_qkv, M_TOT, 3 * DIM, DIM);

    // 2) LN + RoPE + scale + transpose to [B,H,S,D] (tf32-rounded outputs)
    ln_rope_kernel<<<M_TOT, 512>>>(p_qkv, q_g, q_b, k_g, k_b);

    // 3) flash attention (tensor core, ldmatrix, double-buffered K/V)
    const int attn_smem = (AQ * ASTR + 4 * KVBUF) * sizeof(float);  // ~104 KB
    cudaFuncSetAttribute(attn_tc, cudaFuncAttributeMaxDynamicSharedMemorySize, attn_smem);
    attn_tc<<<dim3(S / AQ, B * NHEADS), 256, attn_smem>>>(p_q, p_k, p_v, p_o);

    // 4) output projection: out = O @ w_proj^T + b_proj
    gemm_tf32<<<dim3(DIM / 128, M_TOT / 256), 256, gemm_smem>>>(
        p_o, p_wp, b_proj, out, M_TOT, DIM, DIM);
}